// round 10
// baseline (speedup 1.0000x reference)
#include <cuda_runtime.h>
#include <math.h>

typedef unsigned long long ull;

#define LAT 123
#define DIMA 128
#define HID 256
#define NT 50
#define NSTEP 49
#define NTHR 512
#define MROW 48
#define NBLK 128            // 6144/48, single wave

// smem (ull units): yin[48][128] dup | act[48][128] j2-packed   -> 96 KB, L1 keeps 132 KB
#define ACT_OFF 6144
#define SMEM_ULL 12288
#define SMEM_BYTES (SMEM_ULL*8)   // 98304 B

// packed weights (built once by pack_kernel)
__device__ ull g_w1jp[DIMA*128];   // [d][j2] = (W1[2j2][d], W1[2j2+1][d])
__device__ ull g_w2jp[128*DIMA];   // [j2][d] = (W2[d][2j2], W2[d][2j2+1])
__device__ ull g_b1p[128];         // (b1[2j2], b1[2j2+1])

__device__ __forceinline__ ull pk2(float lo, float hi){
  ull r; asm("mov.b64 %0, {%1, %2};" : "=l"(r) : "f"(lo), "f"(hi)); return r;
}
__device__ __forceinline__ void upk2(ull v, float &lo, float &hi){
  asm("mov.b64 {%0, %1}, %2;" : "=f"(lo), "=f"(hi) : "l"(v));
}
__device__ __forceinline__ ull fma2_(ull a, ull b, ull c){
  ull d; asm("fma.rn.f32x2 %0, %1, %2, %3;" : "=l"(d) : "l"(a), "l"(b), "l"(c)); return d;
}
__device__ __forceinline__ ull add2_(ull a, ull b){
  ull d; asm("add.rn.f32x2 %0, %1, %2;" : "=l"(d) : "l"(a), "l"(b)); return d;
}

__device__ __forceinline__ float fast_tanh(float x){
  float ax = fabsf(x);
  float e = __expf(-2.0f * ax);
  float r = __fdividef(1.0f - e, 1.0f + e);
  return copysignf(r, x);
}
__device__ __forceinline__ ull tanh2p(ull v){
  float lo, hi; upk2(v, lo, hi);
  return pk2(fast_tanh(lo), fast_tanh(hi));
}

__global__ void pack_kernel(const float* __restrict__ W1, const float* __restrict__ W2,
                            const float* __restrict__ b1){
  int i = blockIdx.x*256 + threadIdx.x;      // 0..16383
  int d  = i >> 7, j2 = i & 127;
  g_w1jp[i] = pk2(W1[(2*j2)*DIMA + d], W1[(2*j2+1)*DIMA + d]);
  int j2b = i >> 7, d2 = i & 127;
  g_w2jp[i] = pk2(W2[d2*HID + 2*j2b], W2[d2*HID + 2*j2b+1]);
  if (i < 128) g_b1p[i] = pk2(b1[2*i], b1[2*i+1]);
}

__global__ __launch_bounds__(NTHR,1)
void ode_kernel(const float* __restrict__ fp, const float* __restrict__ ts,
                const float* __restrict__ b2, float* __restrict__ out)
{
  extern __shared__ ull sm[];
  ull* yin = sm;                       // [r][d]  dup(y[r][d]), stride 128
  ull* act = sm + ACT_OFF;             // [r][j2] packed (tanh_{2j2}, tanh_{2j2+1})

  const int tid = threadIdx.x;
  const int lg  = tid & 31;
  const int wp  = tid >> 5;            // warp 0..15; warp owns rows r0..r0+2 end-to-end
  const int r0  = wp*3;
  const int grow = blockIdx.x*MROW + r0;

  const int jA = 2*lg, jB = 64 + 2*lg;   // P1 j2 pair-bases
  const int dA = 2*lg, dB = 64 + 2*lg;   // P2 d bases

  const ull b1A0 = g_b1p[jA], b1A1 = g_b1p[jA+1];
  const ull b1B0 = g_b1p[jB], b1B1 = g_b1p[jB+1];
  const float b2v[4] = { __ldg(b2+dA), __ldg(b2+dA+1), __ldg(b2+dB), __ldg(b2+dB+1) };

  // ---- init: y0 = [first_point | 0], write yin-dup + out[t=0] ----
  float y0r[4][3], k1r[4][3], k2r[4][3];
  #pragma unroll
  for (int rr=0; rr<3; ++rr){
    int g = grow + rr;
    const float* fr = fp + (size_t)g*LAT;
    float v0 = (dA   < LAT) ? __ldg(fr+dA)   : 0.0f;
    float v1 = (dA+1 < LAT) ? __ldg(fr+dA+1) : 0.0f;
    float v2 = (dB   < LAT) ? __ldg(fr+dB)   : 0.0f;
    float v3 = (dB+1 < LAT) ? __ldg(fr+dB+1) : 0.0f;
    y0r[0][rr]=v0; y0r[1][rr]=v1; y0r[2][rr]=v2; y0r[3][rr]=v3;
    ulonglong2 s0; s0.x = pk2(v0,v0); s0.y = pk2(v1,v1);
    ulonglong2 s1; s1.x = pk2(v2,v2); s1.y = pk2(v3,v3);
    *(ulonglong2*)&yin[(r0+rr)*128 + dA] = s0;
    *(ulonglong2*)&yin[(r0+rr)*128 + dB] = s1;
    *(float2*)(out + ((size_t)g*NT)*DIMA + dA) = make_float2(v0,v1);
    *(float2*)(out + ((size_t)g*NT)*DIMA + dB) = make_float2(v2,v3);
  }
  __syncthreads();

  #pragma unroll 1
  for (int step=0; step<NSTEP; ++step){
    const float t0 = __ldg(ts+step);
    const float h  = __ldg(ts+step+1) - t0;

    #pragma unroll 1
    for (int st=0; st<4; ++st){
      // ========= P1: act[r][j2] = tanh(b1 + sum_d W1[j][d]*y[r][d]) =========
      ull acc[4][3];
      #pragma unroll
      for (int i=0;i<4;i++)
        #pragma unroll
        for (int rr=0;rr<3;rr++) acc[i][rr]=0ull;

      {
        const ull* nb = g_w1jp;
        const ull* yb = &yin[r0*128];
        #pragma unroll 2
        for (int cc=0; cc<64; ++cc){
          ulonglong2 w0 = __ldg((const ulonglong2*)(nb+jA));     // (j2=jA,jA+1) @ d=2cc
          ulonglong2 w1 = __ldg((const ulonglong2*)(nb+jB));
          ulonglong2 w2 = __ldg((const ulonglong2*)(nb+128+jA)); // @ d=2cc+1
          ulonglong2 w3 = __ldg((const ulonglong2*)(nb+128+jB));
          #pragma unroll
          for (int rr=0; rr<3; ++rr){
            ulonglong2 yv = *(const ulonglong2*)(yb + rr*128 + 2*cc);  // broadcast
            acc[0][rr]=fma2_(w0.x, yv.x, acc[0][rr]);
            acc[1][rr]=fma2_(w0.y, yv.x, acc[1][rr]);
            acc[2][rr]=fma2_(w1.x, yv.x, acc[2][rr]);
            acc[3][rr]=fma2_(w1.y, yv.x, acc[3][rr]);
            acc[0][rr]=fma2_(w2.x, yv.y, acc[0][rr]);
            acc[1][rr]=fma2_(w2.y, yv.y, acc[1][rr]);
            acc[2][rr]=fma2_(w3.x, yv.y, acc[2][rr]);
            acc[3][rr]=fma2_(w3.y, yv.y, acc[3][rr]);
          }
          nb += 256;
        }
      }
      #pragma unroll
      for (int rr=0; rr<3; ++rr){
        ulonglong2 sA, sB;
        sA.x = tanh2p(add2_(acc[0][rr], b1A0));
        sA.y = tanh2p(add2_(acc[1][rr], b1A1));
        sB.x = tanh2p(add2_(acc[2][rr], b1B0));
        sB.y = tanh2p(add2_(acc[3][rr], b1B1));
        *(ulonglong2*)&act[(r0+rr)*128 + jA] = sA;
        *(ulonglong2*)&act[(r0+rr)*128 + jB] = sB;
      }
      __syncthreads();   // converge warps so W2 stream gets cross-warp L1 reuse

      // ========= P2: k[r][d] = b2 + sum_j W2[d][j]*act[r][j] =========
      ull a2[4][3];
      #pragma unroll
      for (int i=0;i<4;i++)
        #pragma unroll
        for (int rr=0;rr<3;rr++) a2[i][rr]=0ull;

      {
        const ull* nb = g_w2jp;
        const ull* ab = &act[r0*128];
        #pragma unroll 2
        for (int cc=0; cc<64; ++cc){
          ulonglong2 w0 = __ldg((const ulonglong2*)(nb+dA));     // (d=dA,dA+1) @ j2=2cc
          ulonglong2 w1 = __ldg((const ulonglong2*)(nb+dB));
          ulonglong2 w2 = __ldg((const ulonglong2*)(nb+128+dA)); // @ j2=2cc+1
          ulonglong2 w3 = __ldg((const ulonglong2*)(nb+128+dB));
          #pragma unroll
          for (int rr=0; rr<3; ++rr){
            ulonglong2 av = *(const ulonglong2*)(ab + rr*128 + 2*cc);  // broadcast
            a2[0][rr]=fma2_(w0.x, av.x, a2[0][rr]);
            a2[1][rr]=fma2_(w0.y, av.x, a2[1][rr]);
            a2[2][rr]=fma2_(w1.x, av.x, a2[2][rr]);
            a2[3][rr]=fma2_(w1.y, av.x, a2[3][rr]);
            a2[0][rr]=fma2_(w2.x, av.y, a2[0][rr]);
            a2[1][rr]=fma2_(w2.y, av.y, a2[1][rr]);
            a2[2][rr]=fma2_(w3.x, av.y, a2[2][rr]);
            a2[3][rr]=fma2_(w3.y, av.y, a2[3][rr]);
          }
          nb += 256;
        }
      }
      // horizontal add + bias -> k
      float kk[4][3];
      #pragma unroll
      for (int i=0;i<4;i++)
        #pragma unroll
        for (int rr=0;rr<3;rr++){
          float lo, hi; upk2(a2[i][rr], lo, hi);
          kk[i][rr] = lo + hi + b2v[i];
        }

      // ========= RK4(3/8) stage update (all state in registers) =========
      #pragma unroll
      for (int rr=0; rr<3; ++rr){
        float yn[4];
        if (st == 0){
          const float c = h*(1.0f/3.0f);
          #pragma unroll
          for (int i=0;i<4;i++){
            k1r[i][rr] = kk[i][rr];
            yn[i] = fmaf(c, kk[i][rr], y0r[i][rr]);
          }
        } else if (st == 1){
          const float c = -h*(1.0f/3.0f);
          #pragma unroll
          for (int i=0;i<4;i++){
            k2r[i][rr] = kk[i][rr];
            yn[i] = fmaf(c, k1r[i][rr], fmaf(h, kk[i][rr], y0r[i][rr]));
          }
        } else if (st == 2){
          #pragma unroll
          for (int i=0;i<4;i++){
            yn[i] = fmaf(h, k1r[i][rr] - k2r[i][rr] + kk[i][rr], y0r[i][rr]);
            // fold Butcher sum: A = k1 + 3*(k2 + k3) into k2 slot
            k2r[i][rr] = fmaf(3.0f, k2r[i][rr] + kk[i][rr], k1r[i][rr]);
          }
        } else {
          const float c = h*0.125f;
          #pragma unroll
          for (int i=0;i<4;i++){
            yn[i] = fmaf(c, k2r[i][rr] + kk[i][rr], y0r[i][rr]);   // y + h/8*(A + k4)
            y0r[i][rr] = yn[i];
          }
          int g = grow + rr;
          *(float2*)(out + ((size_t)g*NT + step+1)*DIMA + dA) = make_float2(yn[0], yn[1]);
          *(float2*)(out + ((size_t)g*NT + step+1)*DIMA + dB) = make_float2(yn[2], yn[3]);
        }
        ulonglong2 w0; w0.x = pk2(yn[0],yn[0]); w0.y = pk2(yn[1],yn[1]);
        ulonglong2 w1; w1.x = pk2(yn[2],yn[2]); w1.y = pk2(yn[3],yn[3]);
        *(ulonglong2*)&yin[(r0+rr)*128 + dA] = w0;
        *(ulonglong2*)&yin[(r0+rr)*128 + dB] = w1;
      }
      __syncthreads();   // converge before next stage's W1 stream
    }
  }
}

extern "C" void kernel_launch(void* const* d_in, const int* in_sizes, int n_in,
                              void* d_out, int out_size)
{
  const float* fp = (const float*)d_in[0];   // (3,2048,123)
  const float* ts = (const float*)d_in[1];   // (50)
  const float* W1 = (const float*)d_in[2];   // (256,128)
  const float* b1 = (const float*)d_in[3];   // (256)
  const float* W2 = (const float*)d_in[4];   // (128,256)
  const float* b2 = (const float*)d_in[5];   // (128)
  float* out = (float*)d_out;                // (3,2048,50,128)

  pack_kernel<<<64, 256>>>(W1, W2, b1);

  cudaFuncSetAttribute(ode_kernel,
                       cudaFuncAttributeMaxDynamicSharedMemorySize, SMEM_BYTES);
  ode_kernel<<<NBLK, NTHR, SMEM_BYTES>>>(fp, ts, b2, out);
}